// round 1
// baseline (speedup 1.0000x reference)
#include <cuda_runtime.h>
#include <math.h>

#define HIDDEN 1024
#define HEADS  16
#define HD     64
#define SEQ    2048
#define BATCH  4
#define M_TOT  (BATCH*SEQ)   // 8192

// ---------------- scratch (device globals: allocation-free) ----------------
__device__ float g_q[(size_t)M_TOT * HIDDEN];
__device__ float g_k[(size_t)M_TOT * HIDDEN];
__device__ float g_v[(size_t)M_TOT * HIDDEN];
__device__ float g_attn[(size_t)M_TOT * HIDDEN];

// ---------------------------------------------------------------------------
// GEMM: C[m][n] = scale * (sum_k A[m][k] * W[n][k] + bias[n])
// A: [M,K] row-major, W: [N,K] row-major (i.e. computes A @ W^T + b)
// 128x128 tile, BK=16, 256 threads, 8x8 register tile per thread.
// ---------------------------------------------------------------------------
__global__ __launch_bounds__(256) void gemm_wt(
    const float* __restrict__ A, const float* __restrict__ W,
    const float* __restrict__ bias, float* __restrict__ C,
    int M, int N, int K, float scale)
{
    __shared__ float As[16][132];   // [k][m], pad 4 keeps float4 alignment
    __shared__ float Ws[16][132];   // [k][n]

    const int tid = threadIdx.x;
    const int tx = tid & 15;        // 0..15  (n direction)
    const int ty = tid >> 4;        // 0..15  (m direction)
    const int m0 = blockIdx.y * 128;
    const int n0 = blockIdx.x * 128;

    const float* Ap = A + (size_t)m0 * K;
    const float* Wp = W + (size_t)n0 * K;

    float acc[8][8];
    #pragma unroll
    for (int i = 0; i < 8; i++)
        #pragma unroll
        for (int j = 0; j < 8; j++) acc[i][j] = 0.f;

    for (int k0 = 0; k0 < K; k0 += 16) {
        // cooperative load: 128 rows x 16 k = 512 float4 per matrix, 2 per thread
        #pragma unroll
        for (int r = 0; r < 2; r++) {
            int f   = tid + r * 256;     // 0..511
            int row = f >> 2;            // 0..127
            int kq  = (f & 3) << 2;      // 0,4,8,12
            float4 a = *(const float4*)(Ap + (size_t)row * K + k0 + kq);
            As[kq+0][row] = a.x; As[kq+1][row] = a.y;
            As[kq+2][row] = a.z; As[kq+3][row] = a.w;
            float4 w = *(const float4*)(Wp + (size_t)row * K + k0 + kq);
            Ws[kq+0][row] = w.x; Ws[kq+1][row] = w.y;
            Ws[kq+2][row] = w.z; Ws[kq+3][row] = w.w;
        }
        __syncthreads();

        #pragma unroll
        for (int kk = 0; kk < 16; kk++) {
            float a[8], b[8];
            *(float4*)(a+0) = *(const float4*)&As[kk][ty*8+0];
            *(float4*)(a+4) = *(const float4*)&As[kk][ty*8+4];
            *(float4*)(b+0) = *(const float4*)&Ws[kk][tx*8+0];
            *(float4*)(b+4) = *(const float4*)&Ws[kk][tx*8+4];
            #pragma unroll
            for (int i = 0; i < 8; i++)
                #pragma unroll
                for (int j = 0; j < 8; j++)
                    acc[i][j] += a[i] * b[j];
        }
        __syncthreads();
    }

    float bv[8];
    *(float4*)(bv+0) = *(const float4*)&bias[n0 + tx*8 + 0];
    *(float4*)(bv+4) = *(const float4*)&bias[n0 + tx*8 + 4];

    #pragma unroll
    for (int i = 0; i < 8; i++) {
        float* crow = C + (size_t)(m0 + ty*8 + i) * N + n0 + tx*8;
        float4 r0, r1;
        r0.x = scale * (acc[i][0] + bv[0]);
        r0.y = scale * (acc[i][1] + bv[1]);
        r0.z = scale * (acc[i][2] + bv[2]);
        r0.w = scale * (acc[i][3] + bv[3]);
        r1.x = scale * (acc[i][4] + bv[4]);
        r1.y = scale * (acc[i][5] + bv[5]);
        r1.z = scale * (acc[i][6] + bv[6]);
        r1.w = scale * (acc[i][7] + bv[7]);
        *(float4*)(crow + 0) = r0;
        *(float4*)(crow + 4) = r1;
    }
}

// ---------------------------------------------------------------------------
// Flash attention (fp32, online softmax). One block = one (b,h) x 64 queries.
// Q is pre-scaled by 1/sqrt(d) (folded into the Q projection).
// Output written directly in combined [B,S,H*D] layout.
// ---------------------------------------------------------------------------
#define ST 68   // smem row stride (pad 4, keeps float4 alignment)

__global__ __launch_bounds__(256) void attn_kernel(
    const float* __restrict__ Q, const float* __restrict__ Kg,
    const float* __restrict__ Vg, const float* __restrict__ bias,
    float* __restrict__ O)
{
    extern __shared__ float sm[];
    float* Qs = sm;                 // [d][q]  64x68
    float* Ks = Qs + 64 * ST;       // [d][j]  64x68
    float* Vs = Ks + 64 * ST;       // [j][d]  64x68
    float* Ps = Vs + 64 * ST;       // [j][q]  64x68

    const int tid = threadIdx.x;
    const int tx = tid & 15;        // key / head-dim direction (4 each)
    const int ty = tid >> 4;        // query direction (4 each)
    const int q0 = blockIdx.x * 64;
    const int h  = blockIdx.y;
    const int b  = blockIdx.z;
    const size_t base = (size_t)b * SEQ * HIDDEN + (size_t)h * HD;

    // load Q tile transposed: Qs[d][q]
    #pragma unroll
    for (int r = 0; r < 4; r++) {
        int f   = tid + r * 256;     // 0..1023
        int row = f >> 4;            // query 0..63
        int dq  = (f & 15) << 2;     // 0..60
        float4 qv = *(const float4*)(Q + base + (size_t)(q0 + row) * HIDDEN + dq);
        Qs[(dq+0)*ST + row] = qv.x; Qs[(dq+1)*ST + row] = qv.y;
        Qs[(dq+2)*ST + row] = qv.z; Qs[(dq+3)*ST + row] = qv.w;
    }

    float o[4][4];
    float mrow[4], lrow[4];
    #pragma unroll
    for (int i = 0; i < 4; i++) {
        mrow[i] = -1e30f; lrow[i] = 0.f;
        #pragma unroll
        for (int j = 0; j < 4; j++) o[i][j] = 0.f;
    }

    for (int k0 = 0; k0 < SEQ; k0 += 64) {
        __syncthreads();   // prev iter's reads of Ks/Vs/Ps done; Q load done (iter 0)
        // load K tile transposed (Ks[d][j]) and V tile direct (Vs[j][d])
        #pragma unroll
        for (int r = 0; r < 4; r++) {
            int f   = tid + r * 256;
            int row = f >> 4;
            int dq  = (f & 15) << 2;
            float4 kv = *(const float4*)(Kg + base + (size_t)(k0 + row) * HIDDEN + dq);
            Ks[(dq+0)*ST + row] = kv.x; Ks[(dq+1)*ST + row] = kv.y;
            Ks[(dq+2)*ST + row] = kv.z; Ks[(dq+3)*ST + row] = kv.w;
            float4 vv = *(const float4*)(Vg + base + (size_t)(k0 + row) * HIDDEN + dq);
            *(float4*)&Vs[row*ST + dq] = vv;
        }
        __syncthreads();

        // S = Q @ K^T  (4x4 per thread)
        float s[4][4];
        #pragma unroll
        for (int i = 0; i < 4; i++)
            #pragma unroll
            for (int j = 0; j < 4; j++) s[i][j] = 0.f;

        #pragma unroll 8
        for (int d = 0; d < 64; d++) {
            float qv[4], kv[4];
            *(float4*)qv = *(const float4*)&Qs[d*ST + ty*4];
            *(float4*)kv = *(const float4*)&Ks[d*ST + tx*4];
            #pragma unroll
            for (int i = 0; i < 4; i++)
                #pragma unroll
                for (int j = 0; j < 4; j++)
                    s[i][j] += qv[i] * kv[j];
        }

        // + bias[q, k]
        #pragma unroll
        for (int i = 0; i < 4; i++) {
            float4 bv4 = *(const float4*)(bias + (size_t)(q0 + ty*4 + i) * SEQ + k0 + tx*4);
            s[i][0] += bv4.x; s[i][1] += bv4.y; s[i][2] += bv4.z; s[i][3] += bv4.w;
        }

        // online softmax; row r = ty*4+i is shared by the 16 lanes with same ty
        #pragma unroll
        for (int i = 0; i < 4; i++) {
            float mt = fmaxf(fmaxf(s[i][0], s[i][1]), fmaxf(s[i][2], s[i][3]));
            #pragma unroll
            for (int off = 8; off > 0; off >>= 1)
                mt = fmaxf(mt, __shfl_xor_sync(0xffffffffu, mt, off));
            float mnew  = fmaxf(mrow[i], mt);
            float alpha = __expf(mrow[i] - mnew);
            mrow[i] = mnew;
            float sum = 0.f;
            #pragma unroll
            for (int j = 0; j < 4; j++) {
                float p = __expf(s[i][j] - mnew);
                s[i][j] = p;
                sum += p;
            }
            #pragma unroll
            for (int off = 8; off > 0; off >>= 1)
                sum += __shfl_xor_sync(0xffffffffu, sum, off);
            lrow[i] = lrow[i] * alpha + sum;
            #pragma unroll
            for (int j = 0; j < 4; j++) o[i][j] *= alpha;
        }

        // stage P into smem as Ps[j][q] (float4 over the 4 consecutive queries)
        #pragma unroll
        for (int jj = 0; jj < 4; jj++) {
            float4 pv = make_float4(s[0][jj], s[1][jj], s[2][jj], s[3][jj]);
            *(float4*)&Ps[(tx*4 + jj)*ST + ty*4] = pv;
        }
        __syncthreads();

        // O += P @ V  (cols of O = head-dim slice tx*4..+3)
        #pragma unroll 8
        for (int j = 0; j < 64; j++) {
            float pv[4], vv[4];
            *(float4*)pv = *(const float4*)&Ps[j*ST + ty*4];
            *(float4*)vv = *(const float4*)&Vs[j*ST + tx*4];
            #pragma unroll
            for (int i = 0; i < 4; i++)
                #pragma unroll
                for (int jj = 0; jj < 4; jj++)
                    o[i][jj] += pv[i] * vv[jj];
        }
    }

    // normalize and store in combined layout [B,S,H*D]
    #pragma unroll
    for (int i = 0; i < 4; i++) {
        float inv = 1.f / lrow[i];
        float4 ov = make_float4(o[i][0]*inv, o[i][1]*inv, o[i][2]*inv, o[i][3]*inv);
        *(float4*)(O + base + (size_t)(q0 + ty*4 + i) * HIDDEN + tx*4) = ov;
    }
}

// ---------------------------------------------------------------------------
extern "C" void kernel_launch(void* const* d_in, const int* in_sizes, int n_in,
                              void* d_out, int out_size)
{
    (void)in_sizes; (void)n_in; (void)out_size;
    const float* query = (const float*)d_in[0];
    const float* bias  = (const float*)d_in[1];
    const float* wq    = (const float*)d_in[2];
    const float* bq    = (const float*)d_in[3];
    const float* wk    = (const float*)d_in[4];
    const float* bk    = (const float*)d_in[5];
    const float* wv    = (const float*)d_in[6];
    const float* bv    = (const float*)d_in[7];
    const float* wo    = (const float*)d_in[8];
    const float* bo    = (const float*)d_in[9];
    float* out = (float*)d_out;

    float *qb, *kb, *vb, *ab;
    cudaGetSymbolAddress((void**)&qb, g_q);
    cudaGetSymbolAddress((void**)&kb, g_k);
    cudaGetSymbolAddress((void**)&vb, g_v);
    cudaGetSymbolAddress((void**)&ab, g_attn);

    const int smem_attn = 4 * 64 * ST * (int)sizeof(float);  // 69632 B
    cudaFuncSetAttribute(attn_kernel,
                         cudaFuncAttributeMaxDynamicSharedMemorySize, smem_attn);

    dim3 ggrid(HIDDEN / 128, M_TOT / 128);   // (8, 64)
    const float qscale = 0.125f;             // (HIDDEN/HEADS)^-0.5 = 64^-0.5

    gemm_wt<<<ggrid, 256>>>(query, wq, bq, qb, M_TOT, HIDDEN, HIDDEN, qscale);
    gemm_wt<<<ggrid, 256>>>(query, wk, bk, kb, M_TOT, HIDDEN, HIDDEN, 1.0f);
    gemm_wt<<<ggrid, 256>>>(query, wv, bv, vb, M_TOT, HIDDEN, HIDDEN, 1.0f);

    dim3 agrid(SEQ / 64, HEADS, BATCH);      // (32, 16, 4)
    attn_kernel<<<agrid, 256, smem_attn>>>(qb, kb, vb, bias, ab);

    gemm_wt<<<ggrid, 256>>>(ab, wo, bo, out, M_TOT, HIDDEN, HIDDEN, 1.0f);
}

// round 2
// speedup vs baseline: 3.2308x; 3.2308x over previous
#include <cuda_runtime.h>
#include <math.h>

#define HIDDEN 1024
#define HEADS  16
#define HD     64
#define SEQ    2048
#define BATCH  4
#define M_TOT  (BATCH*SEQ)   // 8192

// ---------------- scratch (device globals: allocation-free) ----------------
__device__ float g_q[(size_t)M_TOT * HIDDEN];
__device__ float g_k[(size_t)M_TOT * HIDDEN];
__device__ float g_v[(size_t)M_TOT * HIDDEN];
__device__ float g_attn[(size_t)M_TOT * HIDDEN];
__device__ int   g_bflag[(SEQ/128) * (SEQ/64)];   // 16*32 = 512

// ---------------------------------------------------------------------------
// helpers: tf32 convert + mma.sync m16n8k8 tf32
// ---------------------------------------------------------------------------
__device__ __forceinline__ unsigned f2tf(float x) {
    unsigned r;
    asm("cvt.rna.tf32.f32 %0, %1;" : "=r"(r) : "f"(x));
    return r;
}

__device__ __forceinline__ void mma_tf32(float* c,
    unsigned a0, unsigned a1, unsigned a2, unsigned a3,
    unsigned b0, unsigned b1)
{
    asm volatile(
        "mma.sync.aligned.m16n8k8.row.col.f32.tf32.tf32.f32 "
        "{%0,%1,%2,%3}, {%4,%5,%6,%7}, {%8,%9}, {%0,%1,%2,%3};\n"
        : "+f"(c[0]), "+f"(c[1]), "+f"(c[2]), "+f"(c[3])
        : "r"(a0), "r"(a1), "r"(a2), "r"(a3), "r"(b0), "r"(b1));
}

// ---------------------------------------------------------------------------
// bias tile flags: flag[qt*32+kt] = any nonzero in bias[qt*128..+128][kt*64..+64]
// ---------------------------------------------------------------------------
__global__ __launch_bounds__(256) void bias_flags(const float* __restrict__ bias,
                                                  int* __restrict__ flags)
{
    const int qt = blockIdx.x >> 5;     // 0..15
    const int kt = blockIdx.x & 31;     // 0..31
    const int tid = threadIdx.x;
    bool nz = false;
    #pragma unroll
    for (int r = 0; r < 8; r++) {
        int f   = tid + r * 256;         // 0..2047
        int row = f >> 4;                // 0..127
        int cq  = (f & 15) << 2;         // 0..60
        float4 v = *(const float4*)(bias + (size_t)(qt * 128 + row) * SEQ + kt * 64 + cq);
        nz |= (v.x != 0.f) | (v.y != 0.f) | (v.z != 0.f) | (v.w != 0.f);
    }
    int any = __syncthreads_or((int)nz);
    if (tid == 0) flags[blockIdx.x] = any;
}

// ---------------------------------------------------------------------------
// tf32 GEMM: C[m][n] = scale * (sum_k A[m][k]*W[n][k] + bias[n])
// 128x128x32 tile, 256 threads = 8 warps (2m x 4n), warp tile 64x32.
// ---------------------------------------------------------------------------
#define GK 1024
#define ASTR 36   // BK(32)+4 pad: fragment LDS bank-conflict-free

__global__ __launch_bounds__(256) void gemm_tf32(
    const float* __restrict__ A, const float* __restrict__ W,
    const float* __restrict__ bias, float* __restrict__ C, float scale)
{
    __shared__ unsigned As[128][ASTR];
    __shared__ unsigned Ws[128][ASTR];

    const int tid  = threadIdx.x;
    const int lane = tid & 31;
    const int warp = tid >> 5;
    const int g    = lane >> 2;      // 0..7
    const int tig  = lane & 3;       // 0..3
    const int wm   = (warp >> 2) * 64;
    const int wn   = (warp & 3) * 32;
    const int m0   = blockIdx.y * 128;
    const int n0   = blockIdx.x * 128;

    const float* Ag = A + (size_t)m0 * GK;
    const float* Wg = W + (size_t)n0 * GK;

    const int srow = tid >> 3;        // 0..31
    const int skq  = (tid & 7) << 2;  // 0..28

    float acc[4][4][4];
    #pragma unroll
    for (int i = 0; i < 4; i++)
        #pragma unroll
        for (int j = 0; j < 4; j++)
            #pragma unroll
            for (int e = 0; e < 4; e++) acc[i][j][e] = 0.f;

    float4 pa[4], pw[4];
    #pragma unroll
    for (int r = 0; r < 4; r++) {
        pa[r] = *(const float4*)(Ag + (size_t)(srow + 32 * r) * GK + skq);
        pw[r] = *(const float4*)(Wg + (size_t)(srow + 32 * r) * GK + skq);
    }

    for (int k0 = 0; k0 < GK; k0 += 32) {
        // stage current tile (convert to tf32)
        #pragma unroll
        for (int r = 0; r < 4; r++) {
            int row = srow + 32 * r;
            uint4 ua = make_uint4(f2tf(pa[r].x), f2tf(pa[r].y), f2tf(pa[r].z), f2tf(pa[r].w));
            *(uint4*)&As[row][skq] = ua;
            uint4 uw = make_uint4(f2tf(pw[r].x), f2tf(pw[r].y), f2tf(pw[r].z), f2tf(pw[r].w));
            *(uint4*)&Ws[row][skq] = uw;
        }
        __syncthreads();

        // prefetch next tile
        if (k0 + 32 < GK) {
            #pragma unroll
            for (int r = 0; r < 4; r++) {
                pa[r] = *(const float4*)(Ag + (size_t)(srow + 32 * r) * GK + k0 + 32 + skq);
                pw[r] = *(const float4*)(Wg + (size_t)(srow + 32 * r) * GK + k0 + 32 + skq);
            }
        }

        #pragma unroll
        for (int kt = 0; kt < 4; kt++) {
            const int kb = kt * 8;
            unsigned af[4][4], bf[4][2];
            #pragma unroll
            for (int mt = 0; mt < 4; mt++) {
                int mr = wm + mt * 16 + g;
                af[mt][0] = As[mr][kb + tig];
                af[mt][1] = As[mr + 8][kb + tig];
                af[mt][2] = As[mr][kb + tig + 4];
                af[mt][3] = As[mr + 8][kb + tig + 4];
            }
            #pragma unroll
            for (int nt = 0; nt < 4; nt++) {
                int nr = wn + nt * 8 + g;
                bf[nt][0] = Ws[nr][kb + tig];
                bf[nt][1] = Ws[nr][kb + tig + 4];
            }
            #pragma unroll
            for (int mt = 0; mt < 4; mt++)
                #pragma unroll
                for (int nt = 0; nt < 4; nt++)
                    mma_tf32(acc[mt][nt], af[mt][0], af[mt][1], af[mt][2], af[mt][3],
                             bf[nt][0], bf[nt][1]);
        }
        __syncthreads();
    }

    // epilogue
    #pragma unroll
    for (int mt = 0; mt < 4; mt++) {
        #pragma unroll
        for (int nt = 0; nt < 4; nt++) {
            int ncol = n0 + wn + nt * 8 + 2 * tig;
            float2 bv = *(const float2*)(bias + ncol);
            int r0 = m0 + wm + mt * 16 + g;
            float2 v0 = make_float2(scale * (acc[mt][nt][0] + bv.x),
                                    scale * (acc[mt][nt][1] + bv.y));
            *(float2*)(C + (size_t)r0 * HIDDEN + ncol) = v0;
            float2 v1 = make_float2(scale * (acc[mt][nt][2] + bv.x),
                                    scale * (acc[mt][nt][3] + bv.y));
            *(float2*)(C + (size_t)(r0 + 8) * HIDDEN + ncol) = v1;
        }
    }
}

// ---------------------------------------------------------------------------
// Flash attention with tf32 mma. Block = 128 q rows x one (b,h). 4 warps,
// each warp owns 32 q rows. Key loop in 64-chunks, online softmax on
// C-fragments, P through warp-private smem rows.
// ---------------------------------------------------------------------------
#define QSS 68   // stride for Qs/Ks/Ps (row-indexed-by-g arrays)
#define VSS 72   // stride for Vs (row-indexed-by-tig array)

#define ATTN_SMEM ((128*QSS + 64*QSS + 64*VSS + 128*QSS) * 4)

__global__ __launch_bounds__(128) void attn_tf32(
    const float* __restrict__ Q, const float* __restrict__ K,
    const float* __restrict__ V, const float* __restrict__ bias,
    const int* __restrict__ flags, float* __restrict__ O)
{
    extern __shared__ unsigned sm[];
    unsigned* Qs = sm;                       // [128][QSS]
    unsigned* Ks = Qs + 128 * QSS;           // [64][QSS]
    unsigned* Vs = Ks + 64 * QSS;            // [64][VSS]
    unsigned* Ps = Vs + 64 * VSS;            // [128][QSS]

    const int tid  = threadIdx.x;
    const int lane = tid & 31;
    const int warp = tid >> 5;
    const int g    = lane >> 2;
    const int tig  = lane & 3;
    const int q0   = blockIdx.x * 128;
    const int h    = blockIdx.y;
    const int b    = blockIdx.z;
    const size_t base = (size_t)b * SEQ * HIDDEN + (size_t)h * HD;
    const int qb   = warp * 32;

    const int srow = tid >> 4;          // 0..7
    const int sdq  = (tid & 15) << 2;   // 0..60

    // stage Q tile (128 x 64), tf32, direct row-major
    #pragma unroll
    for (int r = 0; r < 16; r++) {
        int row = srow + 8 * r;
        float4 v = *(const float4*)(Q + base + (size_t)(q0 + row) * HIDDEN + sdq);
        uint4 u = make_uint4(f2tf(v.x), f2tf(v.y), f2tf(v.z), f2tf(v.w));
        *(uint4*)&Qs[row * QSS + sdq] = u;
    }

    float o[2][8][4];
    float mr[2][2], lr[2][2];
    #pragma unroll
    for (int mt = 0; mt < 2; mt++) {
        mr[mt][0] = -1e30f; mr[mt][1] = -1e30f;
        lr[mt][0] = 0.f;    lr[mt][1] = 0.f;
        #pragma unroll
        for (int nt = 0; nt < 8; nt++)
            #pragma unroll
            for (int e = 0; e < 4; e++) o[mt][nt][e] = 0.f;
    }

    for (int c = 0; c < SEQ / 64; c++) {
        const int k0 = c * 64;
        __syncthreads();     // prior chunk's Ks/Vs reads complete
        // stage K (row-major) and V (row-major, stride VSS)
        #pragma unroll
        for (int r = 0; r < 8; r++) {
            int row = srow + 8 * r;
            float4 kv = *(const float4*)(K + base + (size_t)(k0 + row) * HIDDEN + sdq);
            uint4 uk = make_uint4(f2tf(kv.x), f2tf(kv.y), f2tf(kv.z), f2tf(kv.w));
            *(uint4*)&Ks[row * QSS + sdq] = uk;
            float4 vv = *(const float4*)(V + base + (size_t)(k0 + row) * HIDDEN + sdq);
            uint4 uv = make_uint4(f2tf(vv.x), f2tf(vv.y), f2tf(vv.z), f2tf(vv.w));
            *(uint4*)&Vs[row * VSS + sdq] = uv;
        }
        __syncthreads();

        // ---- S = Q @ K^T (m=32 q, n=64 keys, k=64 d) ----
        float s[2][8][4];
        #pragma unroll
        for (int mt = 0; mt < 2; mt++)
            #pragma unroll
            for (int nt = 0; nt < 8; nt++)
                #pragma unroll
                for (int e = 0; e < 4; e++) s[mt][nt][e] = 0.f;

        #pragma unroll
        for (int kt = 0; kt < 8; kt++) {
            const int kb = kt * 8;
            unsigned qf[2][4];
            #pragma unroll
            for (int mt = 0; mt < 2; mt++) {
                int qr = qb + mt * 16 + g;
                qf[mt][0] = Qs[qr * QSS + kb + tig];
                qf[mt][1] = Qs[(qr + 8) * QSS + kb + tig];
                qf[mt][2] = Qs[qr * QSS + kb + tig + 4];
                qf[mt][3] = Qs[(qr + 8) * QSS + kb + tig + 4];
            }
            #pragma unroll
            for (int nt = 0; nt < 8; nt++) {
                int kr = nt * 8 + g;
                unsigned b0 = Ks[kr * QSS + kb + tig];
                unsigned b1 = Ks[kr * QSS + kb + tig + 4];
                #pragma unroll
                for (int mt = 0; mt < 2; mt++)
                    mma_tf32(s[mt][nt], qf[mt][0], qf[mt][1], qf[mt][2], qf[mt][3], b0, b1);
            }
        }

        // ---- bias (skipped when tile is all-zero) ----
        if (flags[blockIdx.x * (SEQ / 64) + c]) {
            #pragma unroll
            for (int mt = 0; mt < 2; mt++) {
                int r0 = q0 + qb + mt * 16 + g;
                #pragma unroll
                for (int nt = 0; nt < 8; nt++) {
                    int col = k0 + nt * 8 + 2 * tig;
                    float2 b0 = *(const float2*)(bias + (size_t)r0 * SEQ + col);
                    s[mt][nt][0] += b0.x; s[mt][nt][1] += b0.y;
                    float2 b1 = *(const float2*)(bias + (size_t)(r0 + 8) * SEQ + col);
                    s[mt][nt][2] += b1.x; s[mt][nt][3] += b1.y;
                }
            }
        }

        // ---- online softmax (rows: mt*16+g and mt*16+g+8) ----
        #pragma unroll
        for (int mt = 0; mt < 2; mt++) {
            #pragma unroll
            for (int h2 = 0; h2 < 2; h2++) {
                float mx = -1e30f;
                #pragma unroll
                for (int nt = 0; nt < 8; nt++)
                    mx = fmaxf(mx, fmaxf(s[mt][nt][2 * h2], s[mt][nt][2 * h2 + 1]));
                mx = fmaxf(mx, __shfl_xor_sync(0xffffffffu, mx, 1));
                mx = fmaxf(mx, __shfl_xor_sync(0xffffffffu, mx, 2));
                float mn = fmaxf(mr[mt][h2], mx);
                float al = __expf(mr[mt][h2] - mn);
                mr[mt][h2] = mn;
                float sum = 0.f;
                #pragma unroll
                for (int nt = 0; nt < 8; nt++) {
                    float p0 = __expf(s[mt][nt][2 * h2]     - mn);
                    float p1 = __expf(s[mt][nt][2 * h2 + 1] - mn);
                    s[mt][nt][2 * h2]     = p0;
                    s[mt][nt][2 * h2 + 1] = p1;
                    sum += p0 + p1;
                }
                sum += __shfl_xor_sync(0xffffffffu, sum, 1);
                sum += __shfl_xor_sync(0xffffffffu, sum, 2);
                lr[mt][h2] = lr[mt][h2] * al + sum;
                #pragma unroll
                for (int nt = 0; nt < 8; nt++) {
                    o[mt][nt][2 * h2]     *= al;
                    o[mt][nt][2 * h2 + 1] *= al;
                }
            }
        }

        // ---- write P to warp-private smem rows (tf32) ----
        #pragma unroll
        for (int mt = 0; mt < 2; mt++) {
            int qr = qb + mt * 16 + g;
            #pragma unroll
            for (int nt = 0; nt < 8; nt++) {
                int col = nt * 8 + 2 * tig;
                uint2 u0 = make_uint2(f2tf(s[mt][nt][0]), f2tf(s[mt][nt][1]));
                *(uint2*)&Ps[qr * QSS + col] = u0;
                uint2 u1 = make_uint2(f2tf(s[mt][nt][2]), f2tf(s[mt][nt][3]));
                *(uint2*)&Ps[(qr + 8) * QSS + col] = u1;
            }
        }
        __syncwarp();

        // ---- O += P @ V (m=32 q, n=64 d, k=64 keys) ----
        #pragma unroll
        for (int kt = 0; kt < 8; kt++) {
            const int kb = kt * 8;
            unsigned pf[2][4];
            #pragma unroll
            for (int mt = 0; mt < 2; mt++) {
                int qr = qb + mt * 16 + g;
                pf[mt][0] = Ps[qr * QSS + kb + tig];
                pf[mt][1] = Ps[(qr + 8) * QSS + kb + tig];
                pf[mt][2] = Ps[qr * QSS + kb + tig + 4];
                pf[mt][3] = Ps[(qr + 8) * QSS + kb + tig + 4];
            }
            #pragma unroll
            for (int nt = 0; nt < 8; nt++) {
                int dcol = nt * 8 + g;
                unsigned b0 = Vs[(kb + tig) * VSS + dcol];
                unsigned b1 = Vs[(kb + tig + 4) * VSS + dcol];
                #pragma unroll
                for (int mt = 0; mt < 2; mt++)
                    mma_tf32(o[mt][nt], pf[mt][0], pf[mt][1], pf[mt][2], pf[mt][3], b0, b1);
            }
        }
    }

    // ---- normalize + store to combined layout [B,S,H*D] ----
    #pragma unroll
    for (int mt = 0; mt < 2; mt++) {
        float inv0 = 1.f / lr[mt][0];
        float inv1 = 1.f / lr[mt][1];
        int r0 = q0 + qb + mt * 16 + g;
        #pragma unroll
        for (int nt = 0; nt < 8; nt++) {
            int col = h * HD + nt * 8 + 2 * tig;
            float2 v0 = make_float2(o[mt][nt][0] * inv0, o[mt][nt][1] * inv0);
            *(float2*)(O + (size_t)b * SEQ * HIDDEN + (size_t)r0 * HIDDEN + col) = v0;
            float2 v1 = make_float2(o[mt][nt][2] * inv1, o[mt][nt][3] * inv1);
            *(float2*)(O + (size_t)b * SEQ * HIDDEN + (size_t)(r0 + 8) * HIDDEN + col) = v1;
        }
    }
}

// ---------------------------------------------------------------------------
extern "C" void kernel_launch(void* const* d_in, const int* in_sizes, int n_in,
                              void* d_out, int out_size)
{
    (void)in_sizes; (void)n_in; (void)out_size;
    const float* query = (const float*)d_in[0];
    const float* bias  = (const float*)d_in[1];
    const float* wq    = (const float*)d_in[2];
    const float* bq    = (const float*)d_in[3];
    const float* wk    = (const float*)d_in[4];
    const float* bk    = (const float*)d_in[5];
    const float* wv    = (const float*)d_in[6];
    const float* bv    = (const float*)d_in[7];
    const float* wo    = (const float*)d_in[8];
    const float* bo    = (const float*)d_in[9];
    float* out = (float*)d_out;

    float *qb, *kb, *vb, *ab;
    int* bfl;
    cudaGetSymbolAddress((void**)&qb, g_q);
    cudaGetSymbolAddress((void**)&kb, g_k);
    cudaGetSymbolAddress((void**)&vb, g_v);
    cudaGetSymbolAddress((void**)&ab, g_attn);
    cudaGetSymbolAddress((void**)&bfl, g_bflag);

    cudaFuncSetAttribute(attn_tf32,
                         cudaFuncAttributeMaxDynamicSharedMemorySize, ATTN_SMEM);

    bias_flags<<<(SEQ/128) * (SEQ/64), 256>>>(bias, bfl);

    dim3 ggrid(HIDDEN / 128, M_TOT / 128);   // (8, 64)
    const float qscale = 0.125f;             // 64^-0.5

    gemm_tf32<<<ggrid, 256>>>(query, wq, bq, qb, qscale);
    gemm_tf32<<<ggrid, 256>>>(query, wk, bk, kb, 1.0f);
    gemm_tf32<<<ggrid, 256>>>(query, wv, bv, vb, 1.0f);

    dim3 agrid(SEQ / 128, HEADS, BATCH);     // (16, 16, 4)
    attn_tf32<<<agrid, 128, ATTN_SMEM>>>(qb, kb, vb, bias, bfl, ab);

    gemm_tf32<<<ggrid, 256>>>(ab, wo, bo, out, 1.0f);
}

// round 3
// speedup vs baseline: 3.2599x; 1.0090x over previous
#include <cuda_runtime.h>
#include <math.h>

#define HIDDEN 1024
#define HEADS  16
#define HD     64
#define SEQ    2048
#define BATCH  4
#define M_TOT  (BATCH*SEQ)   // 8192

// ---------------- scratch (device globals: allocation-free) ----------------
__device__ float g_q[(size_t)M_TOT * HIDDEN];
__device__ float g_k[(size_t)M_TOT * HIDDEN];
__device__ float g_v[(size_t)M_TOT * HIDDEN];
__device__ float g_attn[(size_t)M_TOT * HIDDEN];
__device__ int   g_bflag[(SEQ/128) * (SEQ/64)];   // 16*32 = 512

// ---------------------------------------------------------------------------
// helpers: tf32 convert + mma.sync m16n8k8 tf32
// ---------------------------------------------------------------------------
__device__ __forceinline__ unsigned f2tf(float x) {
    unsigned r;
    asm("cvt.rna.tf32.f32 %0, %1;" : "=r"(r) : "f"(x));
    return r;
}

__device__ __forceinline__ void mma_tf32(float* c,
    unsigned a0, unsigned a1, unsigned a2, unsigned a3,
    unsigned b0, unsigned b1)
{
    asm volatile(
        "mma.sync.aligned.m16n8k8.row.col.f32.tf32.tf32.f32 "
        "{%0,%1,%2,%3}, {%4,%5,%6,%7}, {%8,%9}, {%0,%1,%2,%3};\n"
        : "+f"(c[0]), "+f"(c[1]), "+f"(c[2]), "+f"(c[3])
        : "r"(a0), "r"(a1), "r"(a2), "r"(a3), "r"(b0), "r"(b1));
}

// ---------------------------------------------------------------------------
// bias tile flags: flag[qt*32+kt] = any nonzero in bias[qt*128..+128][kt*64..+64]
// ---------------------------------------------------------------------------
__global__ __launch_bounds__(256) void bias_flags(const float* __restrict__ bias,
                                                  int* __restrict__ flags)
{
    const int qt = blockIdx.x >> 5;
    const int kt = blockIdx.x & 31;
    const int tid = threadIdx.x;
    bool nz = false;
    #pragma unroll
    for (int r = 0; r < 8; r++) {
        int f   = tid + r * 256;
        int row = f >> 4;
        int cq  = (f & 15) << 2;
        float4 v = *(const float4*)(bias + (size_t)(qt * 128 + row) * SEQ + kt * 64 + cq);
        nz |= (v.x != 0.f) | (v.y != 0.f) | (v.z != 0.f) | (v.w != 0.f);
    }
    int any = __syncthreads_or((int)nz);
    if (tid == 0) flags[blockIdx.x] = any;
}

// ---------------------------------------------------------------------------
// tf32 GEMM: C = scale * (A @ W^T + bias). 128x128x32 tile, 256 thr = 8 warps
// (2m x 4n), warp tile 64x32. 2-stage smem double buffer, 1 sync per K-iter.
// ---------------------------------------------------------------------------
#define GK 1024
#define ASTR 36               // BK(32)+4: fragment LDS conflict-free
#define GSTAGE (128*ASTR)     // words per stage per matrix
#define GEMM_SMEM (2 * 2 * GSTAGE * 4)   // 73728 B

__global__ __launch_bounds__(256) void gemm_tf32(
    const float* __restrict__ A, const float* __restrict__ W,
    const float* __restrict__ bias, float* __restrict__ C, float scale)
{
    extern __shared__ unsigned gsm[];
    unsigned* As = gsm;               // [2][128][ASTR]
    unsigned* Ws = gsm + 2 * GSTAGE;  // [2][128][ASTR]

    const int tid  = threadIdx.x;
    const int lane = tid & 31;
    const int warp = tid >> 5;
    const int g    = lane >> 2;
    const int tig  = lane & 3;
    const int wm   = (warp >> 2) * 64;
    const int wn   = (warp & 3) * 32;
    const int m0   = blockIdx.y * 128;
    const int n0   = blockIdx.x * 128;

    const float* Ag = A + (size_t)m0 * GK;
    const float* Wg = W + (size_t)n0 * GK;

    const int srow = tid >> 3;        // 0..31
    const int skq  = (tid & 7) << 2;  // 0..28

    const unsigned* aB = As + (wm + g) * ASTR + tig;
    const unsigned* wB = Ws + (wn + g) * ASTR + tig;

    float acc[4][4][4];
    #pragma unroll
    for (int i = 0; i < 4; i++)
        #pragma unroll
        for (int j = 0; j < 4; j++)
            #pragma unroll
            for (int e = 0; e < 4; e++) acc[i][j][e] = 0.f;

    float4 pa[4], pw[4];
    // prologue: tile 0 -> stage 0
    #pragma unroll
    for (int r = 0; r < 4; r++) {
        pa[r] = *(const float4*)(Ag + (size_t)(srow + 32 * r) * GK + skq);
        pw[r] = *(const float4*)(Wg + (size_t)(srow + 32 * r) * GK + skq);
    }
    #pragma unroll
    for (int r = 0; r < 4; r++) {
        int row = srow + 32 * r;
        *(uint4*)&As[row * ASTR + skq] =
            make_uint4(f2tf(pa[r].x), f2tf(pa[r].y), f2tf(pa[r].z), f2tf(pa[r].w));
        *(uint4*)&Ws[row * ASTR + skq] =
            make_uint4(f2tf(pw[r].x), f2tf(pw[r].y), f2tf(pw[r].z), f2tf(pw[r].w));
    }
    __syncthreads();

    for (int k0 = 0; k0 < GK; k0 += 32) {
        const int cur = (k0 >> 5) & 1;
        const int nxt = cur ^ 1;
        const bool more = (k0 + 32 < GK);

        // issue next tile's LDGs before the MMA chain (latency overlap)
        if (more) {
            #pragma unroll
            for (int r = 0; r < 4; r++) {
                pa[r] = *(const float4*)(Ag + (size_t)(srow + 32 * r) * GK + k0 + 32 + skq);
                pw[r] = *(const float4*)(Wg + (size_t)(srow + 32 * r) * GK + k0 + 32 + skq);
            }
        }

        const unsigned* aS = aB + cur * GSTAGE;
        const unsigned* wS = wB + cur * GSTAGE;
        #pragma unroll
        for (int kt = 0; kt < 4; kt++) {
            const int kb = kt * 8;
            unsigned af[4][4], bf[4][2];
            #pragma unroll
            for (int mt = 0; mt < 4; mt++) {
                const unsigned* p = aS + mt * 16 * ASTR + kb;
                af[mt][0] = p[0];
                af[mt][1] = p[8 * ASTR];
                af[mt][2] = p[4];
                af[mt][3] = p[8 * ASTR + 4];
            }
            #pragma unroll
            for (int nt = 0; nt < 4; nt++) {
                const unsigned* p = wS + nt * 8 * ASTR + kb;
                bf[nt][0] = p[0];
                bf[nt][1] = p[4];
            }
            #pragma unroll
            for (int mt = 0; mt < 4; mt++)
                #pragma unroll
                for (int nt = 0; nt < 4; nt++)
                    mma_tf32(acc[mt][nt], af[mt][0], af[mt][1], af[mt][2], af[mt][3],
                             bf[nt][0], bf[nt][1]);
        }

        if (more) {
            #pragma unroll
            for (int r = 0; r < 4; r++) {
                int row = nxt * GSTAGE + (srow + 32 * r) * ASTR + skq;
                *(uint4*)&As[row] =
                    make_uint4(f2tf(pa[r].x), f2tf(pa[r].y), f2tf(pa[r].z), f2tf(pa[r].w));
                *(uint4*)&Ws[row] =
                    make_uint4(f2tf(pw[r].x), f2tf(pw[r].y), f2tf(pw[r].z), f2tf(pw[r].w));
            }
        }
        __syncthreads();
    }

    // epilogue
    #pragma unroll
    for (int mt = 0; mt < 4; mt++) {
        #pragma unroll
        for (int nt = 0; nt < 4; nt++) {
            int ncol = n0 + wn + nt * 8 + 2 * tig;
            float2 bv = *(const float2*)(bias + ncol);
            int r0 = m0 + wm + mt * 16 + g;
            *(float2*)(C + (size_t)r0 * HIDDEN + ncol) =
                make_float2(scale * (acc[mt][nt][0] + bv.x), scale * (acc[mt][nt][1] + bv.y));
            *(float2*)(C + (size_t)(r0 + 8) * HIDDEN + ncol) =
                make_float2(scale * (acc[mt][nt][2] + bv.x), scale * (acc[mt][nt][3] + bv.y));
        }
    }
}

// ---------------------------------------------------------------------------
// Flash attention, tf32 mma. Block = 128 q rows x (b,h). 256 threads = 8
// warps, warp owns 16 q rows. K/V chunks of 64 keys, 2-stage double buffer,
// one block sync per chunk. P round-trips through warp-private smem rows.
// ---------------------------------------------------------------------------
#define QSS 68
#define VSS 72
#define KCH (64*QSS)   // words per K stage
#define VCH (64*VSS)   // words per V stage
#define ATTN_SMEM ((128*QSS + 128*QSS + 2*KCH + 2*VCH) * 4)   // 141312 B

__global__ __launch_bounds__(256) void attn_tf32(
    const float* __restrict__ Q, const float* __restrict__ K,
    const float* __restrict__ V, const float* __restrict__ bias,
    const int* __restrict__ flags, float* __restrict__ O)
{
    extern __shared__ unsigned sm[];
    unsigned* Qs = sm;                    // [128][QSS]
    unsigned* Ps = Qs + 128 * QSS;        // [128][QSS]
    unsigned* Ks = Ps + 128 * QSS;        // [2][64][QSS]
    unsigned* Vs = Ks + 2 * KCH;          // [2][64][VSS]

    const int tid  = threadIdx.x;
    const int lane = tid & 31;
    const int warp = tid >> 5;           // 0..7
    const int g    = lane >> 2;
    const int tig  = lane & 3;
    const int q0   = blockIdx.x * 128;
    const int h    = blockIdx.y;
    const int b    = blockIdx.z;
    const size_t base = (size_t)b * SEQ * HIDDEN + (size_t)h * HD;
    const int qb   = warp * 16;

    const int srow = tid >> 4;           // 0..15
    const int sdq  = (tid & 15) << 2;    // 0..60

    // stage Q tile (128 x 64)
    #pragma unroll
    for (int r = 0; r < 8; r++) {
        int row = srow + 16 * r;
        float4 v = *(const float4*)(Q + base + (size_t)(q0 + row) * HIDDEN + sdq);
        *(uint4*)&Qs[row * QSS + sdq] =
            make_uint4(f2tf(v.x), f2tf(v.y), f2tf(v.z), f2tf(v.w));
    }

    float4 pk[4], pv4[4];
    // prologue: chunk 0 -> stage 0
    #pragma unroll
    for (int r = 0; r < 4; r++) {
        int row = srow + 16 * r;
        pk[r]  = *(const float4*)(K + base + (size_t)row * HIDDEN + sdq);
        pv4[r] = *(const float4*)(V + base + (size_t)row * HIDDEN + sdq);
    }
    #pragma unroll
    for (int r = 0; r < 4; r++) {
        int row = srow + 16 * r;
        *(uint4*)&Ks[row * QSS + sdq] =
            make_uint4(f2tf(pk[r].x), f2tf(pk[r].y), f2tf(pk[r].z), f2tf(pk[r].w));
        *(uint4*)&Vs[row * VSS + sdq] =
            make_uint4(f2tf(pv4[r].x), f2tf(pv4[r].y), f2tf(pv4[r].z), f2tf(pv4[r].w));
    }
    __syncthreads();

    float o[8][4];
    float mr[2], lr[2];
    mr[0] = mr[1] = -1e30f;
    lr[0] = lr[1] = 0.f;
    #pragma unroll
    for (int nt = 0; nt < 8; nt++)
        #pragma unroll
        for (int e = 0; e < 4; e++) o[nt][e] = 0.f;

    const int qr = qb + g;

    for (int c = 0; c < SEQ / 64; c++) {
        const int cur = c & 1;
        const int nxt = cur ^ 1;
        const bool more = (c + 1 < SEQ / 64);

        // issue next chunk's LDGs early
        if (more) {
            const int k1 = (c + 1) * 64;
            #pragma unroll
            for (int r = 0; r < 4; r++) {
                int row = srow + 16 * r;
                pk[r]  = *(const float4*)(K + base + (size_t)(k1 + row) * HIDDEN + sdq);
                pv4[r] = *(const float4*)(V + base + (size_t)(k1 + row) * HIDDEN + sdq);
            }
        }

        // ---- S = Q @ K^T (16 q x 64 keys x 64 d) ----
        float s[8][4];
        #pragma unroll
        for (int nt = 0; nt < 8; nt++)
            #pragma unroll
            for (int e = 0; e < 4; e++) s[nt][e] = 0.f;

        const unsigned* kS = Ks + cur * KCH;
        #pragma unroll
        for (int kt = 0; kt < 8; kt++) {
            const int kb = kt * 8;
            const unsigned* qp = Qs + qr * QSS + kb + tig;
            unsigned a0 = qp[0], a1 = qp[8 * QSS], a2 = qp[4], a3 = qp[8 * QSS + 4];
            #pragma unroll
            for (int nt = 0; nt < 8; nt++) {
                const unsigned* kp = kS + (nt * 8 + g) * QSS + kb + tig;
                mma_tf32(s[nt], a0, a1, a2, a3, kp[0], kp[4]);
            }
        }

        // ---- bias (skipped when tile all-zero) ----
        if (flags[blockIdx.x * (SEQ / 64) + c]) {
            const int k0 = c * 64;
            int r0 = q0 + qr;
            #pragma unroll
            for (int nt = 0; nt < 8; nt++) {
                int col = k0 + nt * 8 + 2 * tig;
                float2 b0 = *(const float2*)(bias + (size_t)r0 * SEQ + col);
                s[nt][0] += b0.x; s[nt][1] += b0.y;
                float2 b1 = *(const float2*)(bias + (size_t)(r0 + 8) * SEQ + col);
                s[nt][2] += b1.x; s[nt][3] += b1.y;
            }
        }

        // ---- online softmax (rows qr, qr+8) ----
        #pragma unroll
        for (int h2 = 0; h2 < 2; h2++) {
            float mx = -1e30f;
            #pragma unroll
            for (int nt = 0; nt < 8; nt++)
                mx = fmaxf(mx, fmaxf(s[nt][2 * h2], s[nt][2 * h2 + 1]));
            mx = fmaxf(mx, __shfl_xor_sync(0xffffffffu, mx, 1));
            mx = fmaxf(mx, __shfl_xor_sync(0xffffffffu, mx, 2));
            float mn = fmaxf(mr[h2], mx);
            float al = __expf(mr[h2] - mn);
            mr[h2] = mn;
            float sum = 0.f;
            #pragma unroll
            for (int nt = 0; nt < 8; nt++) {
                float p0 = __expf(s[nt][2 * h2]     - mn);
                float p1 = __expf(s[nt][2 * h2 + 1] - mn);
                s[nt][2 * h2] = p0;  s[nt][2 * h2 + 1] = p1;
                sum += p0 + p1;
            }
            sum += __shfl_xor_sync(0xffffffffu, sum, 1);
            sum += __shfl_xor_sync(0xffffffffu, sum, 2);
            lr[h2] = lr[h2] * al + sum;
            #pragma unroll
            for (int nt = 0; nt < 8; nt++) {
                o[nt][2 * h2]     *= al;
                o[nt][2 * h2 + 1] *= al;
            }
        }

        // ---- P -> warp-private smem rows ----
        #pragma unroll
        for (int nt = 0; nt < 8; nt++) {
            int col = nt * 8 + 2 * tig;
            *(uint2*)&Ps[qr * QSS + col] =
                make_uint2(f2tf(s[nt][0]), f2tf(s[nt][1]));
            *(uint2*)&Ps[(qr + 8) * QSS + col] =
                make_uint2(f2tf(s[nt][2]), f2tf(s[nt][3]));
        }
        __syncwarp();

        // ---- O += P @ V (16 q x 64 d x 64 keys) ----
        const unsigned* vS = Vs + cur * VCH;
        #pragma unroll
        for (int kt = 0; kt < 8; kt++) {
            const int kb = kt * 8;
            const unsigned* pp = Ps + qr * QSS + kb + tig;
            unsigned a0 = pp[0], a1 = pp[8 * QSS], a2 = pp[4], a3 = pp[8 * QSS + 4];
            #pragma unroll
            for (int nt = 0; nt < 8; nt++) {
                const unsigned* vp = vS + (kb + tig) * VSS + nt * 8 + g;
                mma_tf32(o[nt], a0, a1, a2, a3, vp[0], vp[4 * VSS]);
            }
        }

        // ---- store next chunk into alternate stage ----
        if (more) {
            #pragma unroll
            for (int r = 0; r < 4; r++) {
                int row = srow + 16 * r;
                *(uint4*)&Ks[nxt * KCH + row * QSS + sdq] =
                    make_uint4(f2tf(pk[r].x), f2tf(pk[r].y), f2tf(pk[r].z), f2tf(pk[r].w));
                *(uint4*)&Vs[nxt * VCH + row * VSS + sdq] =
                    make_uint4(f2tf(pv4[r].x), f2tf(pv4[r].y), f2tf(pv4[r].z), f2tf(pv4[r].w));
            }
        }
        __syncthreads();
    }

    // ---- normalize + store combined layout [B,S,H*D] ----
    float inv0 = 1.f / lr[0];
    float inv1 = 1.f / lr[1];
    int r0 = q0 + qr;
    #pragma unroll
    for (int nt = 0; nt < 8; nt++) {
        int col = h * HD + nt * 8 + 2 * tig;
        *(float2*)(O + (size_t)b * SEQ * HIDDEN + (size_t)r0 * HIDDEN + col) =
            make_float2(o[nt][0] * inv0, o[nt][1] * inv0);
        *(float2*)(O + (size_t)b * SEQ * HIDDEN + (size_t)(r0 + 8) * HIDDEN + col) =
            make_float2(o[nt][2] * inv1, o[nt][3] * inv1);
    }
}

// ---------------------------------------------------------------------------
extern "C" void kernel_launch(void* const* d_in, const int* in_sizes, int n_in,
                              void* d_out, int out_size)
{
    (void)in_sizes; (void)n_in; (void)out_size;
    const float* query = (const float*)d_in[0];
    const float* bias  = (const float*)d_in[1];
    const float* wq    = (const float*)d_in[2];
    const float* bq    = (const float*)d_in[3];
    const float* wk    = (const float*)d_in[4];
    const float* bk    = (const float*)d_in[5];
    const float* wv    = (const float*)d_in[6];
    const float* bv    = (const float*)d_in[7];
    const float* wo    = (const float*)d_in[8];
    const float* bo    = (const float*)d_in[9];
    float* out = (float*)d_out;

    float *qb, *kb, *vb, *ab;
    int* bfl;
    cudaGetSymbolAddress((void**)&qb, g_q);
    cudaGetSymbolAddress((void**)&kb, g_k);
    cudaGetSymbolAddress((void**)&vb, g_v);
    cudaGetSymbolAddress((void**)&ab, g_attn);
    cudaGetSymbolAddress((void**)&bfl, g_bflag);

    cudaFuncSetAttribute(gemm_tf32,
                         cudaFuncAttributeMaxDynamicSharedMemorySize, GEMM_SMEM);
    cudaFuncSetAttribute(attn_tf32,
                         cudaFuncAttributeMaxDynamicSharedMemorySize, ATTN_SMEM);

    bias_flags<<<(SEQ/128) * (SEQ/64), 256>>>(bias, bfl);

    dim3 ggrid(HIDDEN / 128, M_TOT / 128);   // (8, 64)
    const float qscale = 0.125f;             // 64^-0.5

    gemm_tf32<<<ggrid, 256, GEMM_SMEM>>>(query, wq, bq, qb, qscale);
    gemm_tf32<<<ggrid, 256, GEMM_SMEM>>>(query, wk, bk, kb, 1.0f);
    gemm_tf32<<<ggrid, 256, GEMM_SMEM>>>(query, wv, bv, vb, 1.0f);

    dim3 agrid(SEQ / 128, HEADS, BATCH);     // (16, 16, 4)
    attn_tf32<<<agrid, 256, ATTN_SMEM>>>(qb, kb, vb, bias, bfl, ab);

    gemm_tf32<<<ggrid, 256, GEMM_SMEM>>>(ab, wo, bo, out, 1.0f);
}

// round 5
// speedup vs baseline: 3.4944x; 1.0720x over previous
#include <cuda_runtime.h>
#include <cstdint>
#include <math.h>

#define HIDDEN 1024
#define HEADS  16
#define HD     64
#define SEQ    2048
#define BATCH  4
#define M_TOT  (BATCH*SEQ)   // 8192

// ---------------- scratch (device globals: allocation-free) ----------------
__device__ float g_q[(size_t)M_TOT * HIDDEN];
__device__ float g_k[(size_t)M_TOT * HIDDEN];
__device__ float g_v[(size_t)M_TOT * HIDDEN];
__device__ float g_attn[(size_t)M_TOT * HIDDEN];
__device__ int   g_bflag[(SEQ/128) * (SEQ/64)];

// ---------------------------------------------------------------------------
// helpers
// ---------------------------------------------------------------------------
__device__ __forceinline__ unsigned f2tf(float x) {
    unsigned r;
    asm("cvt.rna.tf32.f32 %0, %1;" : "=r"(r) : "f"(x));
    return r;
}

__device__ __forceinline__ void mma_tf32(float* c,
    unsigned a0, unsigned a1, unsigned a2, unsigned a3,
    unsigned b0, unsigned b1)
{
    asm volatile(
        "mma.sync.aligned.m16n8k8.row.col.f32.tf32.tf32.f32 "
        "{%0,%1,%2,%3}, {%4,%5,%6,%7}, {%8,%9}, {%0,%1,%2,%3};\n"
        : "+f"(c[0]), "+f"(c[1]), "+f"(c[2]), "+f"(c[3])
        : "r"(a0), "r"(a1), "r"(a2), "r"(a3), "r"(b0), "r"(b1));
}

__device__ __forceinline__ void ldsm_x4(unsigned* r, uint32_t addr) {
    asm volatile(
        "ldmatrix.sync.aligned.m8n8.x4.shared.b16 {%0,%1,%2,%3}, [%4];"
        : "=r"(r[0]), "=r"(r[1]), "=r"(r[2]), "=r"(r[3])
        : "r"(addr));
}

__device__ __forceinline__ uint32_t smem_u32(const void* p) {
    uint32_t a;
    asm("{ .reg .u64 t; cvta.to.shared.u64 t, %1; cvt.u32.u64 %0, t; }"
        : "=r"(a) : "l"(p));
    return a;
}

// ---------------------------------------------------------------------------
// bias tile flags: flag[qt*32+kt] = any nonzero in 128x64 bias tile
// ---------------------------------------------------------------------------
__global__ __launch_bounds__(256) void bias_flags(const float* __restrict__ bias,
                                                  int* __restrict__ flags)
{
    const int qt = blockIdx.x >> 5;
    const int kt = blockIdx.x & 31;
    const int tid = threadIdx.x;
    bool nz = false;
    #pragma unroll
    for (int r = 0; r < 8; r++) {
        int f   = tid + r * 256;
        int row = f >> 4;
        int cq  = (f & 15) << 2;
        float4 v = *(const float4*)(bias + (size_t)(qt * 128 + row) * SEQ + kt * 64 + cq);
        nz |= (v.x != 0.f) | (v.y != 0.f) | (v.z != 0.f) | (v.w != 0.f);
    }
    int any = __syncthreads_or((int)nz);
    if (tid == 0) flags[blockIdx.x] = any;
}

// ---------------------------------------------------------------------------
// tf32 GEMM: C = scale * (A @ W^T + bias). 128x128x32 tile, 8 warps (2m x 4n),
// warp tile 64x32. Double-buffered smem; ldmatrix fragment loads.
// ---------------------------------------------------------------------------
#define GK 1024
#define ASTR 36               // BK(32)+4: ldmatrix rows land on distinct bank quads
#define GSTAGE (128*ASTR)     // words per stage per matrix
#define GEMM_SMEM (2 * 2 * GSTAGE * 4)   // 73728 B

__global__ __launch_bounds__(256, 2) void gemm_tf32(
    const float* __restrict__ A, const float* __restrict__ W,
    const float* __restrict__ bias, float* __restrict__ C, float scale)
{
    extern __shared__ unsigned gsm[];
    unsigned* As = gsm;               // [2][128][ASTR]
    unsigned* Ws = gsm + 2 * GSTAGE;  // [2][128][ASTR]
    const uint32_t sbA = smem_u32(As);
    const uint32_t sbW = smem_u32(Ws);

    const int tid  = threadIdx.x;
    const int lane = tid & 31;
    const int warp = tid >> 5;
    const int g    = lane >> 2;
    const int tig  = lane & 3;
    const int wm   = (warp >> 2) * 64;
    const int wn   = (warp & 3) * 32;
    const int m0   = blockIdx.y * 128;
    const int n0   = blockIdx.x * 128;

    const float* Ag = A + (size_t)m0 * GK;
    const float* Wg = W + (size_t)n0 * GK;

    const int srow = tid >> 3;        // 0..31
    const int skq  = (tid & 7) << 2;  // 0..28

    // per-lane ldmatrix addressing
    const int rA = (lane & 7) + ((lane >> 3) & 1) * 8;   // row-in-16 (A pattern)
    const int cA = (lane >> 4) * 4;                      // col word
    const uint32_t aoff = (uint32_t)(((wm + rA) * ASTR + cA) * 4);
    const int rB = (lane & 7) + (lane >> 4) * 8;         // row-in-16 (B pattern)
    const int cB = ((lane >> 3) & 1) * 4;
    const uint32_t boff = (uint32_t)(((wn + rB) * ASTR + cB) * 4);

    float acc[4][4][4];
    #pragma unroll
    for (int i = 0; i < 4; i++)
        #pragma unroll
        for (int j = 0; j < 4; j++)
            #pragma unroll
            for (int e = 0; e < 4; e++) acc[i][j][e] = 0.f;

    float4 pa[4], pw[4];
    #pragma unroll
    for (int r = 0; r < 4; r++) {
        pa[r] = *(const float4*)(Ag + (size_t)(srow + 32 * r) * GK + skq);
        pw[r] = *(const float4*)(Wg + (size_t)(srow + 32 * r) * GK + skq);
    }
    #pragma unroll
    for (int r = 0; r < 4; r++) {
        int row = srow + 32 * r;
        *(uint4*)&As[row * ASTR + skq] =
            make_uint4(f2tf(pa[r].x), f2tf(pa[r].y), f2tf(pa[r].z), f2tf(pa[r].w));
        *(uint4*)&Ws[row * ASTR + skq] =
            make_uint4(f2tf(pw[r].x), f2tf(pw[r].y), f2tf(pw[r].z), f2tf(pw[r].w));
    }
    __syncthreads();

    for (int k0 = 0; k0 < GK; k0 += 32) {
        const int cur = (k0 >> 5) & 1;
        const int nxt = cur ^ 1;
        const bool more = (k0 + 32 < GK);

        if (more) {
            #pragma unroll
            for (int r = 0; r < 4; r++) {
                pa[r] = *(const float4*)(Ag + (size_t)(srow + 32 * r) * GK + k0 + 32 + skq);
                pw[r] = *(const float4*)(Wg + (size_t)(srow + 32 * r) * GK + k0 + 32 + skq);
            }
        }

        const uint32_t aStage = sbA + (uint32_t)(cur * GSTAGE * 4) + aoff;
        const uint32_t wStage = sbW + (uint32_t)(cur * GSTAGE * 4) + boff;
        #pragma unroll
        for (int kt = 0; kt < 4; kt++) {
            const uint32_t kbB = (uint32_t)(kt * 8 * 4);
            unsigned af[4][4], bf[2][4];
            #pragma unroll
            for (int mt = 0; mt < 4; mt++)
                ldsm_x4(af[mt], aStage + (uint32_t)(mt * 16 * ASTR * 4) + kbB);
            #pragma unroll
            for (int p = 0; p < 2; p++)
                ldsm_x4(bf[p], wStage + (uint32_t)(p * 16 * ASTR * 4) + kbB);
            #pragma unroll
            for (int mt = 0; mt < 4; mt++) {
                #pragma unroll
                for (int p = 0; p < 2; p++) {
                    mma_tf32(acc[mt][2*p],   af[mt][0], af[mt][1], af[mt][2], af[mt][3],
                             bf[p][0], bf[p][1]);
                    mma_tf32(acc[mt][2*p+1], af[mt][0], af[mt][1], af[mt][2], af[mt][3],
                             bf[p][2], bf[p][3]);
                }
            }
        }

        if (more) {
            #pragma unroll
            for (int r = 0; r < 4; r++) {
                int row = nxt * GSTAGE + (srow + 32 * r) * ASTR + skq;
                *(uint4*)&As[row] =
                    make_uint4(f2tf(pa[r].x), f2tf(pa[r].y), f2tf(pa[r].z), f2tf(pa[r].w));
                *(uint4*)&Ws[row] =
                    make_uint4(f2tf(pw[r].x), f2tf(pw[r].y), f2tf(pw[r].z), f2tf(pw[r].w));
            }
        }
        __syncthreads();
    }

    #pragma unroll
    for (int mt = 0; mt < 4; mt++) {
        #pragma unroll
        for (int nt = 0; nt < 4; nt++) {
            int ncol = n0 + wn + nt * 8 + 2 * tig;
            float2 bv = *(const float2*)(bias + ncol);
            int r0 = m0 + wm + mt * 16 + g;
            *(float2*)(C + (size_t)r0 * HIDDEN + ncol) =
                make_float2(scale * (acc[mt][nt][0] + bv.x), scale * (acc[mt][nt][1] + bv.y));
            *(float2*)(C + (size_t)(r0 + 8) * HIDDEN + ncol) =
                make_float2(scale * (acc[mt][nt][2] + bv.x), scale * (acc[mt][nt][3] + bv.y));
        }
    }
}

// ---------------------------------------------------------------------------
// Flash attention, tf32 mma + ldmatrix fragments. 256 thr = 8 warps, warp owns
// 16 q rows. K/V 64-key chunks, double-buffered. V frags plain LDS.
// ---------------------------------------------------------------------------
#define QSS 68
#define VSS 72
#define KCH (64*QSS)
#define VCH (64*VSS)
#define ATTN_SMEM ((128*QSS + 128*QSS + 2*KCH + 2*VCH) * 4)

__global__ __launch_bounds__(256) void attn_tf32(
    const float* __restrict__ Q, const float* __restrict__ K,
    const float* __restrict__ V, const float* __restrict__ bias,
    const int* __restrict__ flags, float* __restrict__ O)
{
    extern __shared__ unsigned sm[];
    unsigned* Qs = sm;
    unsigned* Ps = Qs + 128 * QSS;
    unsigned* Ks = Ps + 128 * QSS;
    unsigned* Vs = Ks + 2 * KCH;
    const uint32_t sbQ = smem_u32(Qs);
    const uint32_t sbP = smem_u32(Ps);
    const uint32_t sbK = smem_u32(Ks);

    const int tid  = threadIdx.x;
    const int lane = tid & 31;
    const int warp = tid >> 5;
    const int g    = lane >> 2;
    const int tig  = lane & 3;
    const int q0   = blockIdx.x * 128;
    const int h    = blockIdx.y;
    const int b    = blockIdx.z;
    const size_t base = (size_t)b * SEQ * HIDDEN + (size_t)h * HD;
    const int qb   = warp * 16;

    const int srow = tid >> 4;
    const int sdq  = (tid & 15) << 2;

    // per-lane ldmatrix addressing
    const int rA = (lane & 7) + ((lane >> 3) & 1) * 8;
    const int cA = (lane >> 4) * 4;
    const uint32_t qAddr0 = sbQ + (uint32_t)(((qb + rA) * QSS + cA) * 4);
    const uint32_t pAddr0 = sbP + (uint32_t)(((qb + rA) * QSS + cA) * 4);
    const int rB = (lane & 7) + (lane >> 4) * 8;
    const int cB = ((lane >> 3) & 1) * 4;
    const uint32_t kAddr0 = sbK + (uint32_t)((rB * QSS + cB) * 4);

    #pragma unroll
    for (int r = 0; r < 8; r++) {
        int row = srow + 16 * r;
        float4 v = *(const float4*)(Q + base + (size_t)(q0 + row) * HIDDEN + sdq);
        *(uint4*)&Qs[row * QSS + sdq] =
            make_uint4(f2tf(v.x), f2tf(v.y), f2tf(v.z), f2tf(v.w));
    }

    float4 pk[4], pv4[4];
    #pragma unroll
    for (int r = 0; r < 4; r++) {
        int row = srow + 16 * r;
        pk[r]  = *(const float4*)(K + base + (size_t)row * HIDDEN + sdq);
        pv4[r] = *(const float4*)(V + base + (size_t)row * HIDDEN + sdq);
    }
    #pragma unroll
    for (int r = 0; r < 4; r++) {
        int row = srow + 16 * r;
        *(uint4*)&Ks[row * QSS + sdq] =
            make_uint4(f2tf(pk[r].x), f2tf(pk[r].y), f2tf(pk[r].z), f2tf(pk[r].w));
        *(uint4*)&Vs[row * VSS + sdq] =
            make_uint4(f2tf(pv4[r].x), f2tf(pv4[r].y), f2tf(pv4[r].z), f2tf(pv4[r].w));
    }
    __syncthreads();

    float o[8][4];
    float mr[2], lr[2];
    mr[0] = mr[1] = -1e30f;
    lr[0] = lr[1] = 0.f;
    #pragma unroll
    for (int nt = 0; nt < 8; nt++)
        #pragma unroll
        for (int e = 0; e < 4; e++) o[nt][e] = 0.f;

    const int qr = qb + g;

    for (int c = 0; c < SEQ / 64; c++) {
        const int cur = c & 1;
        const int nxt = cur ^ 1;
        const bool more = (c + 1 < SEQ / 64);

        if (more) {
            const int k1 = (c + 1) * 64;
            #pragma unroll
            for (int r = 0; r < 4; r++) {
                int row = srow + 16 * r;
                pk[r]  = *(const float4*)(K + base + (size_t)(k1 + row) * HIDDEN + sdq);
                pv4[r] = *(const float4*)(V + base + (size_t)(k1 + row) * HIDDEN + sdq);
            }
        }

        // ---- S = Q @ K^T ----
        float s[8][4];
        #pragma unroll
        for (int nt = 0; nt < 8; nt++)
            #pragma unroll
            for (int e = 0; e < 4; e++) s[nt][e] = 0.f;

        const uint32_t kStage = kAddr0 + (uint32_t)(cur * KCH * 4);
        #pragma unroll
        for (int kt = 0; kt < 8; kt++) {
            const uint32_t kbB = (uint32_t)(kt * 8 * 4);
            unsigned qf[4], kf[4][4];
            ldsm_x4(qf, qAddr0 + kbB);
            #pragma unroll
            for (int p = 0; p < 4; p++)
                ldsm_x4(kf[p], kStage + (uint32_t)(p * 16 * QSS * 4) + kbB);
            #pragma unroll
            for (int p = 0; p < 4; p++) {
                mma_tf32(s[2*p],   qf[0], qf[1], qf[2], qf[3], kf[p][0], kf[p][1]);
                mma_tf32(s[2*p+1], qf[0], qf[1], qf[2], qf[3], kf[p][2], kf[p][3]);
            }
        }

        // ---- bias (skipped when tile all-zero) ----
        if (flags[blockIdx.x * (SEQ / 64) + c]) {
            const int k0 = c * 64;
            int r0 = q0 + qr;
            #pragma unroll
            for (int nt = 0; nt < 8; nt++) {
                int col = k0 + nt * 8 + 2 * tig;
                float2 b0 = *(const float2*)(bias + (size_t)r0 * SEQ + col);
                s[nt][0] += b0.x; s[nt][1] += b0.y;
                float2 b1 = *(const float2*)(bias + (size_t)(r0 + 8) * SEQ + col);
                s[nt][2] += b1.x; s[nt][3] += b1.y;
            }
        }

        // ---- online softmax ----
        #pragma unroll
        for (int h2 = 0; h2 < 2; h2++) {
            float mx = -1e30f;
            #pragma unroll
            for (int nt = 0; nt < 8; nt++)
                mx = fmaxf(mx, fmaxf(s[nt][2 * h2], s[nt][2 * h2 + 1]));
            mx = fmaxf(mx, __shfl_xor_sync(0xffffffffu, mx, 1));
            mx = fmaxf(mx, __shfl_xor_sync(0xffffffffu, mx, 2));
            float mn = fmaxf(mr[h2], mx);
            float al = __expf(mr[h2] - mn);
            mr[h2] = mn;
            float sum = 0.f;
            #pragma unroll
            for (int nt = 0; nt < 8; nt++) {
                float p0 = __expf(s[nt][2 * h2]     - mn);
                float p1 = __expf(s[nt][2 * h2 + 1] - mn);
                s[nt][2 * h2] = p0;  s[nt][2 * h2 + 1] = p1;
                sum += p0 + p1;
            }
            sum += __shfl_xor_sync(0xffffffffu, sum, 1);
            sum += __shfl_xor_sync(0xffffffffu, sum, 2);
            lr[h2] = lr[h2] * al + sum;
            #pragma unroll
            for (int nt = 0; nt < 8; nt++) {
                o[nt][2 * h2]     *= al;
                o[nt][2 * h2 + 1] *= al;
            }
        }

        // ---- P -> warp-private smem rows ----
        #pragma unroll
        for (int nt = 0; nt < 8; nt++) {
            int col = nt * 8 + 2 * tig;
            *(uint2*)&Ps[qr * QSS + col] =
                make_uint2(f2tf(s[nt][0]), f2tf(s[nt][1]));
            *(uint2*)&Ps[(qr + 8) * QSS + col] =
                make_uint2(f2tf(s[nt][2]), f2tf(s[nt][3]));
        }
        __syncwarp();

        // ---- O += P @ V ----
        const unsigned* vS = Vs + cur * VCH;
        #pragma unroll
        for (int kt = 0; kt < 8; kt++) {
            const int kb = kt * 8;
            unsigned pf[4];
            ldsm_x4(pf, pAddr0 + (uint32_t)(kb * 4));
            #pragma unroll
            for (int nt = 0; nt < 8; nt++) {
                const unsigned* vp = vS + (kb + tig) * VSS + nt * 8 + g;
                mma_tf32(o[nt], pf[0], pf[1], pf[2], pf[3], vp[0], vp[4 * VSS]);
            }
        }

        if (more) {
            #pragma unroll
            for (int r = 0; r < 4; r++) {
                int row = srow + 16 * r;
                *(uint4*)&Ks[nxt * KCH + row * QSS + sdq] =
                    make_uint4(f2tf(pk[r].x), f2tf(pk[r].y), f2tf(pk[r].z), f2tf(pk[r].w));
                *(uint4*)&Vs[nxt * VCH + row * VSS + sdq] =
                    make_uint4(f2tf(pv4[r].x), f2tf(pv4[r].y), f2tf(pv4[r].z), f2tf(pv4[r].w));
            }
        }
        __syncthreads();
    }

    float inv0 = 1.f / lr[0];
    float inv1 = 1.f / lr[1];
    int r0 = q0 + qr;
    #pragma unroll
    for (int nt = 0; nt < 8; nt++) {
        int col = h * HD + nt * 8 + 2 * tig;
        *(float2*)(O + (size_t)b * SEQ * HIDDEN + (size_t)r0 * HIDDEN + col) =
            make_float2(o[nt][0] * inv0, o[nt][1] * inv0);
        *(float2*)(O + (size_t)b * SEQ * HIDDEN + (size_t)(r0 + 8) * HIDDEN + col) =
            make_float2(o[nt][2] * inv1, o[nt][3] * inv1);
    }
}

// ---------------------------------------------------------------------------
extern "C" void kernel_launch(void* const* d_in, const int* in_sizes, int n_in,
                              void* d_out, int out_size)
{
    (void)in_sizes; (void)n_in; (void)out_size;
    const float* query = (const float*)d_in[0];
    const float* bias  = (const float*)d_in[1];
    const float* wq    = (const float*)d_in[2];
    const float* bq    = (const float*)d_in[3];
    const float* wk    = (const float*)d_in[4];
    const float* bk    = (const float*)d_in[5];
    const float* wv    = (const float*)d_in[6];
    const float* bv    = (const float*)d_in[7];
    const float* wo    = (const float*)d_in[8];
    const float* bo    = (const float*)d_in[9];
    float* out = (float*)d_out;

    float *qb, *kb, *vb, *ab;
    int* bfl;
    cudaGetSymbolAddress((void**)&qb, g_q);
    cudaGetSymbolAddress((void**)&kb, g_k);
    cudaGetSymbolAddress((void**)&vb, g_v);
    cudaGetSymbolAddress((void**)&ab, g_attn);
    cudaGetSymbolAddress((void**)&bfl, g_bflag);

    cudaFuncSetAttribute(gemm_tf32,
                         cudaFuncAttributeMaxDynamicSharedMemorySize, GEMM_SMEM);
    cudaFuncSetAttribute(attn_tf32,
                         cudaFuncAttributeMaxDynamicSharedMemorySize, ATTN_SMEM);

    bias_flags<<<(SEQ/128) * (SEQ/64), 256>>>(bias, bfl);

    dim3 ggrid(HIDDEN / 128, M_TOT / 128);   // (8, 64)
    const float qscale = 0.125f;             // 64^-0.5

    gemm_tf32<<<ggrid, 256, GEMM_SMEM>>>(query, wq, bq, qb, qscale);
    gemm_tf32<<<ggrid, 256, GEMM_SMEM>>>(query, wk, bk, kb, 1.0f);
    gemm_tf32<<<ggrid, 256, GEMM_SMEM>>>(query, wv, bv, vb, 1.0f);

    dim3 agrid(SEQ / 128, HEADS, BATCH);     // (16, 16, 4)
    attn_tf32<<<agrid, 256, ATTN_SMEM>>>(qb, kb, vb, bias, bfl, ab);

    gemm_tf32<<<ggrid, 256, GEMM_SMEM>>>(ab, wo, bo, out, 1.0f);
}

// round 6
// speedup vs baseline: 3.7717x; 1.0793x over previous
#include <cuda_runtime.h>
#include <cstdint>
#include <math.h>

#define HIDDEN 1024
#define HEADS  16
#define HD     64
#define SEQ    2048
#define BATCH  4
#define M_TOT  (BATCH*SEQ)   // 8192

// ---------------- scratch (device globals: allocation-free) ----------------
__device__ float g_q[(size_t)M_TOT * HIDDEN];
__device__ float g_k[(size_t)M_TOT * HIDDEN];
__device__ float g_v[(size_t)M_TOT * HIDDEN];
__device__ float g_attn[(size_t)M_TOT * HIDDEN];
__device__ int   g_bflag[(SEQ/128) * (SEQ/64)];

// ---------------------------------------------------------------------------
// helpers
// ---------------------------------------------------------------------------
__device__ __forceinline__ unsigned f2tf(float x) {
    unsigned r;
    asm("cvt.rna.tf32.f32 %0, %1;" : "=r"(r) : "f"(x));
    return r;
}

__device__ __forceinline__ void mma_tf32(float* c,
    unsigned a0, unsigned a1, unsigned a2, unsigned a3,
    unsigned b0, unsigned b1)
{
    asm volatile(
        "mma.sync.aligned.m16n8k8.row.col.f32.tf32.tf32.f32 "
        "{%0,%1,%2,%3}, {%4,%5,%6,%7}, {%8,%9}, {%0,%1,%2,%3};\n"
        : "+f"(c[0]), "+f"(c[1]), "+f"(c[2]), "+f"(c[3])
        : "r"(a0), "r"(a1), "r"(a2), "r"(a3), "r"(b0), "r"(b1));
}

__device__ __forceinline__ void ldsm_x4(unsigned* r, uint32_t addr) {
    asm volatile(
        "ldmatrix.sync.aligned.m8n8.x4.shared.b16 {%0,%1,%2,%3}, [%4];"
        : "=r"(r[0]), "=r"(r[1]), "=r"(r[2]), "=r"(r[3])
        : "r"(addr));
}

__device__ __forceinline__ uint32_t smem_u32(const void* p) {
    uint32_t a;
    asm("{ .reg .u64 t; cvta.to.shared.u64 t, %1; cvt.u32.u64 %0, t; }"
        : "=r"(a) : "l"(p));
    return a;
}

// ---------------------------------------------------------------------------
// bias tile flags: flag[qt*32+kt] = any nonzero in 128x64 bias tile
// ---------------------------------------------------------------------------
__global__ __launch_bounds__(256) void bias_flags(const float* __restrict__ bias,
                                                  int* __restrict__ flags)
{
    const int qt = blockIdx.x >> 5;
    const int kt = blockIdx.x & 31;
    const int tid = threadIdx.x;
    bool nz = false;
    #pragma unroll
    for (int r = 0; r < 8; r++) {
        int f   = tid + r * 256;
        int row = f >> 4;
        int cq  = (f & 15) << 2;
        float4 v = *(const float4*)(bias + (size_t)(qt * 128 + row) * SEQ + kt * 64 + cq);
        nz |= (v.x != 0.f) | (v.y != 0.f) | (v.z != 0.f) | (v.w != 0.f);
    }
    int any = __syncthreads_or((int)nz);
    if (tid == 0) flags[blockIdx.x] = any;
}

// ---------------------------------------------------------------------------
// tf32 GEMM (unchanged from R5): C = scale * (A @ W^T + bias). 128x128x32
// tile, 8 warps (2m x 4n), double-buffered smem, ldmatrix fragments.
// ---------------------------------------------------------------------------
#define GK 1024
#define ASTR 36
#define GSTAGE (128*ASTR)
#define GEMM_SMEM (2 * 2 * GSTAGE * 4)   // 73728 B

__global__ __launch_bounds__(256, 2) void gemm_tf32(
    const float* __restrict__ A, const float* __restrict__ W,
    const float* __restrict__ bias, float* __restrict__ C, float scale)
{
    extern __shared__ unsigned gsm[];
    unsigned* As = gsm;
    unsigned* Ws = gsm + 2 * GSTAGE;
    const uint32_t sbA = smem_u32(As);
    const uint32_t sbW = smem_u32(Ws);

    const int tid  = threadIdx.x;
    const int lane = tid & 31;
    const int warp = tid >> 5;
    const int g    = lane >> 2;
    const int tig  = lane & 3;
    const int wm   = (warp >> 2) * 64;
    const int wn   = (warp & 3) * 32;
    const int m0   = blockIdx.y * 128;
    const int n0   = blockIdx.x * 128;

    const float* Ag = A + (size_t)m0 * GK;
    const float* Wg = W + (size_t)n0 * GK;

    const int srow = tid >> 3;
    const int skq  = (tid & 7) << 2;

    const int rA = (lane & 7) + ((lane >> 3) & 1) * 8;
    const int cA = (lane >> 4) * 4;
    const uint32_t aoff = (uint32_t)(((wm + rA) * ASTR + cA) * 4);
    const int rB = (lane & 7) + (lane >> 4) * 8;
    const int cB = ((lane >> 3) & 1) * 4;
    const uint32_t boff = (uint32_t)(((wn + rB) * ASTR + cB) * 4);

    float acc[4][4][4];
    #pragma unroll
    for (int i = 0; i < 4; i++)
        #pragma unroll
        for (int j = 0; j < 4; j++)
            #pragma unroll
            for (int e = 0; e < 4; e++) acc[i][j][e] = 0.f;

    float4 pa[4], pw[4];
    #pragma unroll
    for (int r = 0; r < 4; r++) {
        pa[r] = *(const float4*)(Ag + (size_t)(srow + 32 * r) * GK + skq);
        pw[r] = *(const float4*)(Wg + (size_t)(srow + 32 * r) * GK + skq);
    }
    #pragma unroll
    for (int r = 0; r < 4; r++) {
        int row = srow + 32 * r;
        *(uint4*)&As[row * ASTR + skq] =
            make_uint4(f2tf(pa[r].x), f2tf(pa[r].y), f2tf(pa[r].z), f2tf(pa[r].w));
        *(uint4*)&Ws[row * ASTR + skq] =
            make_uint4(f2tf(pw[r].x), f2tf(pw[r].y), f2tf(pw[r].z), f2tf(pw[r].w));
    }
    __syncthreads();

    for (int k0 = 0; k0 < GK; k0 += 32) {
        const int cur = (k0 >> 5) & 1;
        const int nxt = cur ^ 1;
        const bool more = (k0 + 32 < GK);

        if (more) {
            #pragma unroll
            for (int r = 0; r < 4; r++) {
                pa[r] = *(const float4*)(Ag + (size_t)(srow + 32 * r) * GK + k0 + 32 + skq);
                pw[r] = *(const float4*)(Wg + (size_t)(srow + 32 * r) * GK + k0 + 32 + skq);
            }
        }

        const uint32_t aStage = sbA + (uint32_t)(cur * GSTAGE * 4) + aoff;
        const uint32_t wStage = sbW + (uint32_t)(cur * GSTAGE * 4) + boff;
        #pragma unroll
        for (int kt = 0; kt < 4; kt++) {
            const uint32_t kbB = (uint32_t)(kt * 8 * 4);
            unsigned af[4][4], bf[2][4];
            #pragma unroll
            for (int mt = 0; mt < 4; mt++)
                ldsm_x4(af[mt], aStage + (uint32_t)(mt * 16 * ASTR * 4) + kbB);
            #pragma unroll
            for (int p = 0; p < 2; p++)
                ldsm_x4(bf[p], wStage + (uint32_t)(p * 16 * ASTR * 4) + kbB);
            #pragma unroll
            for (int mt = 0; mt < 4; mt++) {
                #pragma unroll
                for (int p = 0; p < 2; p++) {
                    mma_tf32(acc[mt][2*p],   af[mt][0], af[mt][1], af[mt][2], af[mt][3],
                             bf[p][0], bf[p][1]);
                    mma_tf32(acc[mt][2*p+1], af[mt][0], af[mt][1], af[mt][2], af[mt][3],
                             bf[p][2], bf[p][3]);
                }
            }
        }

        if (more) {
            #pragma unroll
            for (int r = 0; r < 4; r++) {
                int row = nxt * GSTAGE + (srow + 32 * r) * ASTR + skq;
                *(uint4*)&As[row] =
                    make_uint4(f2tf(pa[r].x), f2tf(pa[r].y), f2tf(pa[r].z), f2tf(pa[r].w));
                *(uint4*)&Ws[row] =
                    make_uint4(f2tf(pw[r].x), f2tf(pw[r].y), f2tf(pw[r].z), f2tf(pw[r].w));
            }
        }
        __syncthreads();
    }

    #pragma unroll
    for (int mt = 0; mt < 4; mt++) {
        #pragma unroll
        for (int nt = 0; nt < 4; nt++) {
            int ncol = n0 + wn + nt * 8 + 2 * tig;
            float2 bv = *(const float2*)(bias + ncol);
            int r0 = m0 + wm + mt * 16 + g;
            *(float2*)(C + (size_t)r0 * HIDDEN + ncol) =
                make_float2(scale * (acc[mt][nt][0] + bv.x), scale * (acc[mt][nt][1] + bv.y));
            *(float2*)(C + (size_t)(r0 + 8) * HIDDEN + ncol) =
                make_float2(scale * (acc[mt][nt][2] + bv.x), scale * (acc[mt][nt][3] + bv.y));
        }
    }
}

// ---------------------------------------------------------------------------
// Flash attention, tf32 mma + ldmatrix. SINGLE-buffered K/V (103KB smem) so
// 2 CTAs/SM run concurrently -> 16 warps/SM. Register prefetch of the next
// chunk hides global latency; two syncs per chunk.
// ---------------------------------------------------------------------------
#define QSS 68
#define VSS 72
#define ATTN_SMEM ((128*QSS + 128*QSS + 64*QSS + 64*VSS) * 4)   // 105472 B

__global__ __launch_bounds__(256, 2) void attn_tf32(
    const float* __restrict__ Q, const float* __restrict__ K,
    const float* __restrict__ V, const float* __restrict__ bias,
    const int* __restrict__ flags, float* __restrict__ O)
{
    extern __shared__ unsigned sm[];
    unsigned* Qs = sm;                    // [128][QSS]
    unsigned* Ps = Qs + 128 * QSS;        // [128][QSS]
    unsigned* Ks = Ps + 128 * QSS;        // [64][QSS]
    unsigned* Vs = Ks + 64 * QSS;         // [64][VSS]
    const uint32_t sbQ = smem_u32(Qs);
    const uint32_t sbP = smem_u32(Ps);
    const uint32_t sbK = smem_u32(Ks);

    const int tid  = threadIdx.x;
    const int lane = tid & 31;
    const int warp = tid >> 5;
    const int g    = lane >> 2;
    const int tig  = lane & 3;
    const int q0   = blockIdx.x * 128;
    const int h    = blockIdx.y;
    const int b    = blockIdx.z;
    const size_t base = (size_t)b * SEQ * HIDDEN + (size_t)h * HD;
    const int qb   = warp * 16;

    const int srow = tid >> 4;
    const int sdq  = (tid & 15) << 2;

    const int rA = (lane & 7) + ((lane >> 3) & 1) * 8;
    const int cA = (lane >> 4) * 4;
    const uint32_t qAddr0 = sbQ + (uint32_t)(((qb + rA) * QSS + cA) * 4);
    const uint32_t pAddr0 = sbP + (uint32_t)(((qb + rA) * QSS + cA) * 4);
    const int rB = (lane & 7) + (lane >> 4) * 8;
    const int cB = ((lane >> 3) & 1) * 4;
    const uint32_t kAddr0 = sbK + (uint32_t)((rB * QSS + cB) * 4);

    // stage Q tile
    #pragma unroll
    for (int r = 0; r < 8; r++) {
        int row = srow + 16 * r;
        float4 v = *(const float4*)(Q + base + (size_t)(q0 + row) * HIDDEN + sdq);
        *(uint4*)&Qs[row * QSS + sdq] =
            make_uint4(f2tf(v.x), f2tf(v.y), f2tf(v.z), f2tf(v.w));
    }

    // stage chunk 0 K/V
    float4 pk[4], pv4[4];
    #pragma unroll
    for (int r = 0; r < 4; r++) {
        int row = srow + 16 * r;
        pk[r]  = *(const float4*)(K + base + (size_t)row * HIDDEN + sdq);
        pv4[r] = *(const float4*)(V + base + (size_t)row * HIDDEN + sdq);
    }
    #pragma unroll
    for (int r = 0; r < 4; r++) {
        int row = srow + 16 * r;
        *(uint4*)&Ks[row * QSS + sdq] =
            make_uint4(f2tf(pk[r].x), f2tf(pk[r].y), f2tf(pk[r].z), f2tf(pk[r].w));
        *(uint4*)&Vs[row * VSS + sdq] =
            make_uint4(f2tf(pv4[r].x), f2tf(pv4[r].y), f2tf(pv4[r].z), f2tf(pv4[r].w));
    }
    __syncthreads();

    float o[8][4];
    float mr[2], lr[2];
    mr[0] = mr[1] = -1e30f;
    lr[0] = lr[1] = 0.f;
    #pragma unroll
    for (int nt = 0; nt < 8; nt++)
        #pragma unroll
        for (int e = 0; e < 4; e++) o[nt][e] = 0.f;

    const int qr = qb + g;

    for (int c = 0; c < SEQ / 64; c++) {
        const bool more = (c + 1 < SEQ / 64);

        // prefetch next chunk into registers (latency hidden under MMAs)
        if (more) {
            const int k1 = (c + 1) * 64;
            #pragma unroll
            for (int r = 0; r < 4; r++) {
                int row = srow + 16 * r;
                pk[r]  = *(const float4*)(K + base + (size_t)(k1 + row) * HIDDEN + sdq);
                pv4[r] = *(const float4*)(V + base + (size_t)(k1 + row) * HIDDEN + sdq);
            }
        }

        // ---- S = Q @ K^T ----
        float s[8][4];
        #pragma unroll
        for (int nt = 0; nt < 8; nt++)
            #pragma unroll
            for (int e = 0; e < 4; e++) s[nt][e] = 0.f;

        #pragma unroll
        for (int kt = 0; kt < 8; kt++) {
            const uint32_t kbB = (uint32_t)(kt * 8 * 4);
            unsigned qf[4], kf[4][4];
            ldsm_x4(qf, qAddr0 + kbB);
            #pragma unroll
            for (int p = 0; p < 4; p++)
                ldsm_x4(kf[p], kAddr0 + (uint32_t)(p * 16 * QSS * 4) + kbB);
            #pragma unroll
            for (int p = 0; p < 4; p++) {
                mma_tf32(s[2*p],   qf[0], qf[1], qf[2], qf[3], kf[p][0], kf[p][1]);
                mma_tf32(s[2*p+1], qf[0], qf[1], qf[2], qf[3], kf[p][2], kf[p][3]);
            }
        }

        // ---- bias (skipped when tile all-zero) ----
        if (flags[blockIdx.x * (SEQ / 64) + c]) {
            const int k0 = c * 64;
            int r0 = q0 + qr;
            #pragma unroll
            for (int nt = 0; nt < 8; nt++) {
                int col = k0 + nt * 8 + 2 * tig;
                float2 b0 = *(const float2*)(bias + (size_t)r0 * SEQ + col);
                s[nt][0] += b0.x; s[nt][1] += b0.y;
                float2 b1 = *(const float2*)(bias + (size_t)(r0 + 8) * SEQ + col);
                s[nt][2] += b1.x; s[nt][3] += b1.y;
            }
        }

        // ---- online softmax ----
        #pragma unroll
        for (int h2 = 0; h2 < 2; h2++) {
            float mx = -1e30f;
            #pragma unroll
            for (int nt = 0; nt < 8; nt++)
                mx = fmaxf(mx, fmaxf(s[nt][2 * h2], s[nt][2 * h2 + 1]));
            mx = fmaxf(mx, __shfl_xor_sync(0xffffffffu, mx, 1));
            mx = fmaxf(mx, __shfl_xor_sync(0xffffffffu, mx, 2));
            float mn = fmaxf(mr[h2], mx);
            float al = __expf(mr[h2] - mn);
            mr[h2] = mn;
            float sum = 0.f;
            #pragma unroll
            for (int nt = 0; nt < 8; nt++) {
                float p0 = __expf(s[nt][2 * h2]     - mn);
                float p1 = __expf(s[nt][2 * h2 + 1] - mn);
                s[nt][2 * h2] = p0;  s[nt][2 * h2 + 1] = p1;
                sum += p0 + p1;
            }
            sum += __shfl_xor_sync(0xffffffffu, sum, 1);
            sum += __shfl_xor_sync(0xffffffffu, sum, 2);
            lr[h2] = lr[h2] * al + sum;
            #pragma unroll
            for (int nt = 0; nt < 8; nt++) {
                o[nt][2 * h2]     *= al;
                o[nt][2 * h2 + 1] *= al;
            }
        }

        // ---- P -> warp-private smem rows ----
        #pragma unroll
        for (int nt = 0; nt < 8; nt++) {
            int col = nt * 8 + 2 * tig;
            *(uint2*)&Ps[qr * QSS + col] =
                make_uint2(f2tf(s[nt][0]), f2tf(s[nt][1]));
            *(uint2*)&Ps[(qr + 8) * QSS + col] =
                make_uint2(f2tf(s[nt][2]), f2tf(s[nt][3]));
        }
        __syncwarp();

        // ---- O += P @ V ----
        #pragma unroll
        for (int kt = 0; kt < 8; kt++) {
            const int kb = kt * 8;
            unsigned pf[4];
            ldsm_x4(pf, pAddr0 + (uint32_t)(kb * 4));
            #pragma unroll
            for (int nt = 0; nt < 8; nt++) {
                const unsigned* vp = Vs + (kb + tig) * VSS + nt * 8 + g;
                mma_tf32(o[nt], pf[0], pf[1], pf[2], pf[3], vp[0], vp[4 * VSS]);
            }
        }

        // ---- overwrite K/V with the prefetched next chunk ----
        if (more) {
            __syncthreads();   // all warps done reading Ks/Vs
            #pragma unroll
            for (int r = 0; r < 4; r++) {
                int row = srow + 16 * r;
                *(uint4*)&Ks[row * QSS + sdq] =
                    make_uint4(f2tf(pk[r].x), f2tf(pk[r].y), f2tf(pk[r].z), f2tf(pk[r].w));
                *(uint4*)&Vs[row * VSS + sdq] =
                    make_uint4(f2tf(pv4[r].x), f2tf(pv4[r].y), f2tf(pv4[r].z), f2tf(pv4[r].w));
            }
            __syncthreads();
        }
    }

    float inv0 = 1.f / lr[0];
    float inv1 = 1.f / lr[1];
    int r0 = q0 + qr;
    #pragma unroll
    for (int nt = 0; nt < 8; nt++) {
        int col = h * HD + nt * 8 + 2 * tig;
        *(float2*)(O + (size_t)b * SEQ * HIDDEN + (size_t)r0 * HIDDEN + col) =
            make_float2(o[nt][0] * inv0, o[nt][1] * inv0);
        *(float2*)(O + (size_t)b * SEQ * HIDDEN + (size_t)(r0 + 8) * HIDDEN + col) =
            make_float2(o[nt][2] * inv1, o[nt][3] * inv1);
    }
}

// ---------------------------------------------------------------------------
extern "C" void kernel_launch(void* const* d_in, const int* in_sizes, int n_in,
                              void* d_out, int out_size)
{
    (void)in_sizes; (void)n_in; (void)out_size;
    const float* query = (const float*)d_in[0];
    const float* bias  = (const float*)d_in[1];
    const float* wq    = (const float*)d_in[2];
    const float* bq    = (const float*)d_in[3];
    const float* wk    = (const float*)d_in[4];
    const float* bk    = (const float*)d_in[5];
    const float* wv    = (const float*)d_in[6];
    const float* bv    = (const float*)d_in[7];
    const float* wo    = (const float*)d_in[8];
    const float* bo    = (const float*)d_in[9];
    float* out = (float*)d_out;

    float *qb, *kb, *vb, *ab;
    int* bfl;
    cudaGetSymbolAddress((void**)&qb, g_q);
    cudaGetSymbolAddress((void**)&kb, g_k);
    cudaGetSymbolAddress((void**)&vb, g_v);
    cudaGetSymbolAddress((void**)&ab, g_attn);
    cudaGetSymbolAddress((void**)&bfl, g_bflag);

    cudaFuncSetAttribute(gemm_tf32,
                         cudaFuncAttributeMaxDynamicSharedMemorySize, GEMM_SMEM);
    cudaFuncSetAttribute(attn_tf32,
                         cudaFuncAttributeMaxDynamicSharedMemorySize, ATTN_SMEM);

    bias_flags<<<(SEQ/128) * (SEQ/64), 256>>>(bias, bfl);

    dim3 ggrid(HIDDEN / 128, M_TOT / 128);   // (8, 64)
    const float qscale = 0.125f;             // 64^-0.5

    gemm_tf32<<<ggrid, 256, GEMM_SMEM>>>(query, wq, bq, qb, qscale);
    gemm_tf32<<<ggrid, 256, GEMM_SMEM>>>(query, wk, bk, kb, 1.0f);
    gemm_tf32<<<ggrid, 256, GEMM_SMEM>>>(query, wv, bv, vb, 1.0f);

    dim3 agrid(SEQ / 128, HEADS, BATCH);     // (16, 16, 4)
    attn_tf32<<<agrid, 256, ATTN_SMEM>>>(qb, kb, vb, bias, bfl, ab);

    gemm_tf32<<<ggrid, 256, GEMM_SMEM>>>(ab, wo, bo, out, 1.0f);
}